// round 16
// baseline (speedup 1.0000x reference)
#include <cuda_runtime.h>
#include <cuda_bf16.h>
#include <math.h>
#include <stdint.h>

#define BB 64
#define TT 1024
#define INF 512
#define HH 768
#define GG 3072          // 4*H
#define MM (BB*TT)       // 65536
#define OUTD 100
#define BBHH (BB*HH)

// recurrence config
#define NCTA 128
#define JC 6             // h columns per CTA
#define NC 24            // gate rows per CTA (4*JC)
#define KCH 128          // k per chunk
#define WROWB 1552       // W smem row pitch bytes (768*2 + 16)
#define HROW2 272        // h tile row pitch bytes (128*2 + 16)
#define HTILE2 (64*HROW2) // 17408
#define WTILE (NC*WROWB) // 37248
#define RSMEM (2*WTILE + 6*HTILE2 + 2*64*28*4)   // 193280

// GEMM config (fused 4-tile stages, ring-2)
#define HROWB 144        // GEMM tile row pitch (64*2 + 16)
#define GAT (128*HROWB)  // 18432 bytes: one 128x64 bf16 tile
#define GSTAGE (4*GAT)   // Ah, Al, Bh, Bl
#define GSMEM (2*GSTAGE) // 147456

// ---------------- scratch (device globals; no allocation allowed) ----------------
// t-major layout: row(b,t) = t*BB + b
__device__ float g_pre[(size_t)MM * GG];
__device__ float g_proj[(size_t)MM * 128];
__device__ __nv_bfloat16 g_hb[2][BBHH];      // [parity] hi only
__device__ unsigned g_count = 0;             // grid barrier arrivals
__device__ unsigned g_epoch = 0;             // grid barrier epoch (monotonic)
// activation hi/lo pairs (ping-pong between layers), t-major rows
__device__ __nv_bfloat16 g_p0h[(size_t)MM * HH];
__device__ __nv_bfloat16 g_p0l[(size_t)MM * HH];
__device__ __nv_bfloat16 g_p1h[(size_t)MM * HH];
__device__ __nv_bfloat16 g_p1l[(size_t)MM * HH];
// weight splits
__device__ __nv_bfloat16 g_bh[(size_t)GG * HH];
__device__ __nv_bfloat16 g_bl[(size_t)GG * HH];
__device__ __nv_bfloat16 g_ph[128 * HH];
__device__ __nv_bfloat16 g_pl[128 * HH];

// ---------------- ptx helpers (base sm_103 ISA only) ----------------
__device__ __forceinline__ void cpasync16(uint32_t saddr, const void* g) {
    asm volatile("cp.async.cg.shared.global [%0], [%1], 16;\n" :: "r"(saddr), "l"(g));
}
__device__ __forceinline__ void cpcommit() { asm volatile("cp.async.commit_group;\n"); }
template<int N> __device__ __forceinline__ void cpwait() {
    asm volatile("cp.async.wait_group %0;\n" :: "n"(N));
}
__device__ __forceinline__ uint32_t smem_u32(const void* p) {
    return (uint32_t)__cvta_generic_to_shared(p);
}
__device__ __forceinline__ void barsync(int id) {
    asm volatile("bar.sync %0, 128;" :: "r"(id) : "memory");
}
__device__ __forceinline__ void ldsm4(uint32_t addr, uint32_t* r) {
    asm volatile("ldmatrix.sync.aligned.m8n8.x4.shared.b16 {%0,%1,%2,%3}, [%4];"
                 : "=r"(r[0]), "=r"(r[1]), "=r"(r[2]), "=r"(r[3]) : "r"(addr));
}
__device__ __forceinline__ void ldsm2(uint32_t addr, uint32_t* r) {
    asm volatile("ldmatrix.sync.aligned.m8n8.x2.shared.b16 {%0,%1}, [%2];"
                 : "=r"(r[0]), "=r"(r[1]) : "r"(addr));
}
__device__ __forceinline__ void mma_bf16(float* d, const uint32_t* a, uint32_t b0, uint32_t b1) {
    asm volatile(
        "mma.sync.aligned.m16n8k16.row.col.f32.bf16.bf16.f32 "
        "{%0,%1,%2,%3}, {%4,%5,%6,%7}, {%8,%9}, {%0,%1,%2,%3};"
        : "+f"(d[0]), "+f"(d[1]), "+f"(d[2]), "+f"(d[3])
        : "r"(a[0]), "r"(a[1]), "r"(a[2]), "r"(a[3]), "r"(b0), "r"(b1));
}

// fast sigmoid / tanh (clamped, no-NaN; err ~1e-6)
__device__ __forceinline__ float fsigmoid(float x) {
    return __fdividef(1.f, 1.f + __expf(-x));
}
__device__ __forceinline__ float ftanh(float x) {
    x = fminf(15.f, fmaxf(-15.f, x));
    float e2 = __expf(2.f * x);
    return __fdividef(e2 - 1.f, e2 + 1.f);
}

// ---------------- software grid barrier (proven flat atomic) ----------------
__device__ __forceinline__ void grid_barrier(unsigned e0, unsigned target) {
    __threadfence();
    __syncthreads();
    if (threadIdx.x == 0) {
        unsigned a = atomicAdd(&g_count, 1);
        if (a == NCTA - 1) {
            g_count = 0;
            __threadfence();
            atomicAdd(&g_epoch, 1);
        } else {
            while ((*(volatile unsigned*)&g_epoch) - e0 < target) { }
            __threadfence();
        }
    }
    __syncthreads();
}

// ---------------- split conversions ----------------
// transposing split for input x: src rows b*TT+t (b-major) -> dst rows t*BB+b
__global__ void split_x_tmajor(const float* __restrict__ src,
                               __nv_bfloat16* __restrict__ hi,
                               __nv_bfloat16* __restrict__ lo)
{
    const int F4 = INF / 4;   // 128 float4 per row
    size_t n = (size_t)MM * F4;
    size_t i = (size_t)blockIdx.x * blockDim.x + threadIdx.x;
    size_t stride = (size_t)gridDim.x * blockDim.x;
    for (; i < n; i += stride) {
        size_t r = i / F4;
        int off = (int)(i - r * F4);
        int t = (int)(r / BB), b = (int)(r - (size_t)t * BB);
        float4 v = ((const float4*)src)[((size_t)b * TT + t) * F4 + off];
        __nv_bfloat16 h0 = __float2bfloat16(v.x);
        __nv_bfloat16 h1 = __float2bfloat16(v.y);
        __nv_bfloat16 h2 = __float2bfloat16(v.z);
        __nv_bfloat16 h3 = __float2bfloat16(v.w);
        __nv_bfloat162 hp0; hp0.x = h0; hp0.y = h1;
        __nv_bfloat162 hp1; hp1.x = h2; hp1.y = h3;
        __nv_bfloat162 lp0;
        lp0.x = __float2bfloat16(v.x - __bfloat162float(h0));
        lp0.y = __float2bfloat16(v.y - __bfloat162float(h1));
        __nv_bfloat162 lp1;
        lp1.x = __float2bfloat16(v.z - __bfloat162float(h2));
        lp1.y = __float2bfloat16(v.w - __bfloat162float(h3));
        ((__nv_bfloat162*)hi)[2*i]   = hp0;
        ((__nv_bfloat162*)hi)[2*i+1] = hp1;
        ((__nv_bfloat162*)lo)[2*i]   = lp0;
        ((__nv_bfloat162*)lo)[2*i+1] = lp1;
    }
}

__global__ void split_bf16(const float* __restrict__ src,
                           __nv_bfloat16* __restrict__ hi,
                           __nv_bfloat16* __restrict__ lo, size_t n4)
{
    size_t i = (size_t)blockIdx.x * blockDim.x + threadIdx.x;
    size_t stride = (size_t)gridDim.x * blockDim.x;
    for (; i < n4; i += stride) {
        float4 v = ((const float4*)src)[i];
        __nv_bfloat16 h0 = __float2bfloat16(v.x);
        __nv_bfloat16 h1 = __float2bfloat16(v.y);
        __nv_bfloat16 h2 = __float2bfloat16(v.z);
        __nv_bfloat16 h3 = __float2bfloat16(v.w);
        __nv_bfloat162 hp0; hp0.x = h0; hp0.y = h1;
        __nv_bfloat162 hp1; hp1.x = h2; hp1.y = h3;
        __nv_bfloat162 lp0;
        lp0.x = __float2bfloat16(v.x - __bfloat162float(h0));
        lp0.y = __float2bfloat16(v.y - __bfloat162float(h1));
        __nv_bfloat162 lp1;
        lp1.x = __float2bfloat16(v.z - __bfloat162float(h2));
        lp1.y = __float2bfloat16(v.w - __bfloat162float(h3));
        ((__nv_bfloat162*)hi)[2*i]   = hp0;
        ((__nv_bfloat162*)hi)[2*i+1] = hp1;
        ((__nv_bfloat162*)lo)[2*i]   = lp0;
        ((__nv_bfloat162*)lo)[2*i+1] = lp1;
    }
}

__global__ void pad_wp_split(__nv_bfloat16* __restrict__ ph,
                             __nv_bfloat16* __restrict__ pl,
                             const float* __restrict__ Wp)
{
    int i = blockIdx.x * blockDim.x + threadIdx.x;
    int stride = gridDim.x * blockDim.x;
    for (; i < 128 * HH; i += stride) {
        int o = i / HH, k = i % HH;
        float v = (o < OUTD) ? Wp[o * HH + k] : 0.f;
        __nv_bfloat16 h = __float2bfloat16(v);
        ph[i] = h;
        pl[i] = __float2bfloat16(v - __bfloat162float(h));
    }
}

// ---------------- bf16x3 GEMM, fused passes, ring-2 (R10-proven) ----------------
__device__ __forceinline__ void gemm_issue4(uint32_t sb, int stage,
                                            const __nv_bfloat16* Ah, const __nv_bfloat16* Al,
                                            const __nv_bfloat16* Bh, const __nv_bfloat16* Bl,
                                            int m0, int n0, int K, int ck, int tid)
{
    uint32_t base = sb + stage * GSTAGE;
    const __nv_bfloat16* srcs[4] = {
        Ah + (size_t)m0 * K + ck, Al + (size_t)m0 * K + ck,
        Bh + (size_t)n0 * K + ck, Bl + (size_t)n0 * K + ck };
#pragma unroll
    for (int tile = 0; tile < 4; tile++) {
        uint32_t dst = base + tile * GAT;
        const __nv_bfloat16* src = srcs[tile];
#pragma unroll
        for (int it = 0; it < 4; it++) {
            int idx = it * 256 + tid;
            int row = idx >> 3, seg = idx & 7;
            cpasync16(dst + row * HROWB + seg * 16, src + (size_t)row * K + seg * 8);
        }
    }
    cpcommit();
}

__global__ __launch_bounds__(256)
void gemm_mma3(const __nv_bfloat16* __restrict__ Ah, const __nv_bfloat16* __restrict__ Al,
               const __nv_bfloat16* __restrict__ Bh, const __nv_bfloat16* __restrict__ Bl,
               const float* __restrict__ bias, float* __restrict__ C,
               int K, int Ntot)
{
    extern __shared__ __align__(128) char gsm[];
    uint32_t sb = smem_u32(gsm);

    int tid = threadIdx.x;
    int lane = tid & 31;
    int wid = tid >> 5;
    int wm = wid & 3;
    int wn = wid >> 2;
    int m0 = blockIdx.y * 128;
    int n0 = blockIdx.x * 128;

    const int cps = K >> 6;

    float acc[2][8][4];
#pragma unroll
    for (int mt = 0; mt < 2; mt++)
#pragma unroll
        for (int f = 0; f < 8; f++)
#pragma unroll
            for (int r = 0; r < 4; r++) acc[mt][f][r] = 0.f;

    int aRow = (lane & 15);
    int aHalf = (lane >> 4) * 16;
    int gB = lane >> 3;
    int bHalf = (gB & 1) * 16;

    gemm_issue4(sb, 0, Ah, Al, Bh, Bl, m0, n0, K, 0, tid);
    if (cps > 1) gemm_issue4(sb, 1, Ah, Al, Bh, Bl, m0, n0, K, 64, tid);

    for (int c = 0; c < cps; c++) {
        int stage = c & 1;
        if (c + 1 < cps) cpwait<1>(); else cpwait<0>();
        __syncthreads();
        uint32_t tAh = sb + stage * GSTAGE;
        uint32_t tAl = tAh + GAT;
        uint32_t tBh = tAh + 2 * GAT;
        uint32_t tBl = tAh + 3 * GAT;
#pragma unroll
        for (int kk = 0; kk < 4; kk++) {
            uint32_t ah[2][4], al[2][4];
#pragma unroll
            for (int mt = 0; mt < 2; mt++) {
                ldsm4(tAh + (wm*32 + mt*16 + aRow) * HROWB + aHalf + kk*32, ah[mt]);
                ldsm4(tAl + (wm*32 + mt*16 + aRow) * HROWB + aHalf + kk*32, al[mt]);
            }
            uint32_t bh[8][2], bl[8][2];
#pragma unroll
            for (int fp = 0; fp < 4; fp++) {
                int fi = fp * 2 + (gB >> 1);
                uint32_t roff = (wn*64 + fi*8 + (lane & 7)) * HROWB + bHalf + kk*32;
                uint32_t r4[4];
                ldsm4(tBh + roff, r4);
                bh[fp*2][0]   = r4[0]; bh[fp*2][1]   = r4[1];
                bh[fp*2+1][0] = r4[2]; bh[fp*2+1][1] = r4[3];
                ldsm4(tBl + roff, r4);
                bl[fp*2][0]   = r4[0]; bl[fp*2][1]   = r4[1];
                bl[fp*2+1][0] = r4[2]; bl[fp*2+1][1] = r4[3];
            }
#pragma unroll
            for (int mt = 0; mt < 2; mt++)
#pragma unroll
                for (int f = 0; f < 8; f++) {
                    mma_bf16(acc[mt][f], ah[mt], bh[f][0], bh[f][1]);
                    mma_bf16(acc[mt][f], ah[mt], bl[f][0], bl[f][1]);
                    mma_bf16(acc[mt][f], al[mt], bh[f][0], bh[f][1]);
                }
        }
        __syncthreads();
        if (c + 2 < cps)
            gemm_issue4(sb, stage, Ah, Al, Bh, Bl, m0, n0, K, (c + 2) * 64, tid);
    }

    int g4 = lane >> 2, tig = lane & 3;
#pragma unroll
    for (int mt = 0; mt < 2; mt++) {
#pragma unroll
        for (int f = 0; f < 8; f++) {
            int r0 = m0 + wm*32 + mt*16 + g4;
            int c0 = n0 + wn*64 + f*8 + tig*2;
            float b0 = bias ? bias[c0] : 0.f;
            float b1 = bias ? bias[c0+1] : 0.f;
            float2 v0; v0.x = acc[mt][f][0] + b0; v0.y = acc[mt][f][1] + b1;
            float2 v1; v1.x = acc[mt][f][2] + b0; v1.y = acc[mt][f][3] + b1;
            *(float2*)&C[(size_t)r0 * Ntot + c0] = v0;
            *(float2*)&C[(size_t)(r0 + 8) * Ntot + c0] = v1;
        }
    }
}

// ---------------- persistent LSTM: 256 threads, split-K, h hi-only ----------------
// t-major: row(b,t) = t*BB + b. Step t's pre/res/y traffic is one dense block.
__device__ __forceinline__ void rec_issue(uint32_t hbA, int slot,
                                          const __nv_bfloat16* hhi,
                                          int k0, int ltid)
{
    uint32_t dH = hbA + slot * HTILE2;
#pragma unroll
    for (int it = 0; it < 8; it++) {
        int idx = it * 128 + ltid;        // 1024 granules, 128 threads
        int row = idx >> 4, seg = idx & 15;
        cpasync16(dH + row * HROW2 + seg * 16, hhi + (size_t)row * HH + k0 + seg * 8);
    }
    cpcommit();
}

__global__ __launch_bounds__(256, 1)
void lstm_persist(const float* __restrict__ pre, const float* __restrict__ Whh,
                  __nv_bfloat16* __restrict__ hb,
                  __nv_bfloat16* __restrict__ yh, __nv_bfloat16* __restrict__ yl,
                  const __nv_bfloat16* __restrict__ resh,
                  const __nv_bfloat16* __restrict__ resl)
{
    extern __shared__ __align__(128) char rsm[];
    char* Whi = rsm;
    char* Wlo = rsm + WTILE;
    char* Hb  = rsm + 2 * WTILE;                        // 6 slots, hi only
    float* Csm0 = (float*)(rsm + 2 * WTILE + 6 * HTILE2);
    float* Csm1 = Csm0 + 64 * 28;

    int tid = threadIdx.x;
    int lane = tid & 31;
    int wid = tid >> 5;
    int gid = wid >> 2;          // warp group 0/1
    int w = wid & 3;             // row group within warp group
    int ltid = tid & 127;
    int j0 = blockIdx.x * JC;
    unsigned e0 = 0;
    if (tid == 0) e0 = *(volatile unsigned*)&g_epoch;

    float* CsmMy = gid ? Csm1 : Csm0;

    // cache Whh slice as bf16 hi/lo. SMEM row r = gate r/JC, col j0 + r%JC.
    for (int i = tid; i < NC * HH; i += 256) {
        int r = i / HH, k = i - r * HH;
        int g = r / JC, jj = r - g * JC;
        float v = Whh[(size_t)(g * HH + j0 + jj) * HH + k];
        __nv_bfloat16 h = __float2bfloat16(v);
        ((__nv_bfloat16*)(Whi + r * WROWB))[k] = h;
        ((__nv_bfloat16*)(Wlo + r * WROWB))[k] = __float2bfloat16(v - __bfloat162float(h));
    }

    // zero h (parity 0) for owned columns
    if (tid < BB) {
        __nv_bfloat16 z = __float2bfloat16(0.f);
#pragma unroll
        for (int jj = 0; jj < JC; jj++)
            hb[tid * HH + j0 + jj] = z;
    }
    grid_barrier(e0, 1);

    uint32_t hbA = smem_u32(Hb);
    uint32_t wA[2] = { smem_u32(Whi), smem_u32(Wlo) };

    // ldmatrix address components (proven layout)
    int aRow = (lane & 15);
    int aHalf = (lane >> 4) * 16;
    int gB = lane >> 3;
    int fi01 = (gB >> 1) * 8 + (lane & 7);
    int bHalf01 = (gB & 1) * 16;
    int row2 = 16 + (lane & 7);
    int bHalf2 = ((lane >> 3) & 1) * 16;
    int g4 = lane >> 2, tig = lane & 3;

    // cell-update partition
    int b0c = tid / JC, j0c = tid - b0c * JC;
    int b1c = (256 + tid) / JC, j1c = (256 + tid) - b1c * JC;
    bool has2 = (tid < 128);
    float cr0 = 0.f, cr1 = 0.f;

    // preload pre/res for t=0
    float pr0[4], pr1[4], rv0 = 0.f, rv1 = 0.f;
    {
        int jj = j0 + j0c;
        size_t prow = (size_t)b0c * GG;   // t=0: row = b
        pr0[0] = pre[prow + 0*HH + jj];
        pr0[1] = pre[prow + 1*HH + jj];
        pr0[2] = pre[prow + 2*HH + jj];
        pr0[3] = pre[prow + 3*HH + jj];
        if (resh) {
            size_t ri = (size_t)b0c * HH + jj;
            rv0 = __bfloat162float(resh[ri]) + __bfloat162float(resl[ri]);
        }
    }
    if (has2) {
        int jj = j0 + j1c;
        size_t prow = (size_t)b1c * GG;
        pr1[0] = pre[prow + 0*HH + jj];
        pr1[1] = pre[prow + 1*HH + jj];
        pr1[2] = pre[prow + 2*HH + jj];
        pr1[3] = pre[prow + 3*HH + jj];
        if (resh) {
            size_t ri = (size_t)b1c * HH + jj;
            rv1 = __bfloat162float(resh[ri]) + __bfloat162float(resl[ri]);
        }
    }

    for (int t = 0; t < TT; t++) {
        int pin = t & 1;
        const __nv_bfloat16* hin = hb + (size_t)pin * BBHH;
        __nv_bfloat16* hout = hb + (size_t)(pin ^ 1) * BBHH;

        // issue all 3 group chunks up-front (slots gid*3 .. gid*3+2)
        rec_issue(hbA, gid * 3 + 0, hin, (gid * 3 + 0) * KCH, ltid);
        rec_issue(hbA, gid * 3 + 1, hin, (gid * 3 + 1) * KCH, ltid);
        rec_issue(hbA, gid * 3 + 2, hin, (gid * 3 + 2) * KCH, ltid);

        float acc[3][4];
#pragma unroll
        for (int f = 0; f < 3; f++)
#pragma unroll
            for (int r = 0; r < 4; r++) acc[f][r] = 0.f;

        // group-local chunk loop: 3 chunks, one barsync each
#pragma unroll
        for (int i = 0; i < 3; i++) {
            int c = gid * 3 + i;
            int slot = gid * 3 + i;
            if (i == 0) cpwait<2>();
            else if (i == 1) cpwait<1>();
            else cpwait<0>();
            barsync(1 + gid);
            uint32_t Abase = hbA + slot * HTILE2;
            uint32_t Whc = wA[0] + c * 256;
            uint32_t Wlc = wA[1] + c * 256;
#pragma unroll
            for (int kk = 0; kk < 8; kk++) {
                uint32_t a[4];
                ldsm4(Abase + (w*16 + aRow) * HROW2 + aHalf + kk*32, a);
                uint32_t bh01[4], bh2[2], bl01[4], bl2[2];
                ldsm4(Whc + fi01 * WROWB + bHalf01 + kk*32, bh01);
                ldsm2(Whc + row2 * WROWB + bHalf2 + kk*32, bh2);
                ldsm4(Wlc + fi01 * WROWB + bHalf01 + kk*32, bl01);
                ldsm2(Wlc + row2 * WROWB + bHalf2 + kk*32, bl2);
                mma_bf16(acc[0], a, bh01[0], bh01[1]);
                mma_bf16(acc[1], a, bh01[2], bh01[3]);
                mma_bf16(acc[2], a, bh2[0], bh2[1]);
                mma_bf16(acc[0], a, bl01[0], bl01[1]);
                mma_bf16(acc[1], a, bl01[2], bl01[3]);
                mma_bf16(acc[2], a, bl2[0], bl2[1]);
            }
        }

        // write partial gate tile to this group's Csm region
#pragma unroll
        for (int f = 0; f < 3; f++) {
            CsmMy[(w*16 + g4) * 28 + f*8 + tig*2]     = acc[f][0];
            CsmMy[(w*16 + g4) * 28 + f*8 + tig*2 + 1] = acc[f][1];
            CsmMy[(w*16 + 8 + g4) * 28 + f*8 + tig*2]     = acc[f][2];
            CsmMy[(w*16 + 8 + g4) * 28 + f*8 + tig*2 + 1] = acc[f][3];
        }
        __syncthreads();

        // cell update (c in registers); y written as bf16 hi/lo only (t-major)
        {
            int b = b0c, jj = j0c, j = j0 + jj;
            float gi = Csm0[b*28 + 0*JC + jj] + Csm1[b*28 + 0*JC + jj] + pr0[0];
            float gf = Csm0[b*28 + 1*JC + jj] + Csm1[b*28 + 1*JC + jj] + pr0[1];
            float gg = Csm0[b*28 + 2*JC + jj] + Csm1[b*28 + 2*JC + jj] + pr0[2];
            float go = Csm0[b*28 + 3*JC + jj] + Csm1[b*28 + 3*JC + jj] + pr0[3];
            float si = fsigmoid(gi), sf_ = fsigmoid(gf), so = fsigmoid(go);
            float tg = ftanh(gg);
            float cn = sf_ * cr0 + si * tg;
            float hn = so * ftanh(cn);
            cr0 = cn;
            hout[b * HH + j] = __float2bfloat16(hn);
            float yv = resh ? hn + rv0 : hn;
            size_t yi = ((size_t)t * BB + b) * HH + j;
            __nv_bfloat16 vh = __float2bfloat16(yv);
            yh[yi] = vh;
            yl[yi] = __float2bfloat16(yv - __bfloat162float(vh));
        }
        if (has2) {
            int b = b1c, jj = j1c, j = j0 + jj;
            float gi = Csm0[b*28 + 0*JC + jj] + Csm1[b*28 + 0*JC + jj] + pr1[0];
            float gf = Csm0[b*28 + 1*JC + jj] + Csm1[b*28 + 1*JC + jj] + pr1[1];
            float gg = Csm0[b*28 + 2*JC + jj] + Csm1[b*28 + 2*JC + jj] + pr1[2];
            float go = Csm0[b*28 + 3*JC + jj] + Csm1[b*28 + 3*JC + jj] + pr1[3];
            float si = fsigmoid(gi), sf_ = fsigmoid(gf), so = fsigmoid(go);
            float tg = ftanh(gg);
            float cn = sf_ * cr1 + si * tg;
            float hn = so * ftanh(cn);
            cr1 = cn;
            hout[b * HH + j] = __float2bfloat16(hn);
            float yv = resh ? hn + rv1 : hn;
            size_t yi = ((size_t)t * BB + b) * HH + j;
            __nv_bfloat16 vh = __float2bfloat16(yv);
            yh[yi] = vh;
            yl[yi] = __float2bfloat16(yv - __bfloat162float(vh));
        }

        // issue next step's pre/res loads BEFORE the barrier (dense t-major rows)
        if (t + 1 < TT) {
            int tn = t + 1;
            {
                int jj = j0 + j0c;
                size_t prow = ((size_t)tn * BB + b0c) * GG;
                pr0[0] = pre[prow + 0*HH + jj];
                pr0[1] = pre[prow + 1*HH + jj];
                pr0[2] = pre[prow + 2*HH + jj];
                pr0[3] = pre[prow + 3*HH + jj];
                if (resh) {
                    size_t ri = ((size_t)tn * BB + b0c) * HH + jj;
                    rv0 = __bfloat162float(resh[ri]) + __bfloat162float(resl[ri]);
                }
            }
            if (has2) {
                int jj = j0 + j1c;
                size_t prow = ((size_t)tn * BB + b1c) * GG;
                pr1[0] = pre[prow + 0*HH + jj];
                pr1[1] = pre[prow + 1*HH + jj];
                pr1[2] = pre[prow + 2*HH + jj];
                pr1[3] = pre[prow + 3*HH + jj];
                if (resh) {
                    size_t ri = ((size_t)tn * BB + b1c) * HH + jj;
                    rv1 = __bfloat162float(resh[ri]) + __bfloat162float(resl[ri]);
                }
            }
        }
        grid_barrier(e0, t + 2);
    }
}

// ---------------- output copy (un-permute t-major -> b-major) ----------------
__global__ void copy_out(float* __restrict__ out, const float* __restrict__ proj, int n)
{
    int i = blockIdx.x * blockDim.x + threadIdx.x;
    int stride = gridDim.x * blockDim.x;
    for (; i < n; i += stride) {
        int m = i / OUTD, o = i - m * OUTD;    // m = b*TT + t (output order)
        int b = m / TT, t = m - b * TT;
        out[i] = proj[((size_t)t * BB + b) * 128 + o];
    }
}

// ---------------- driver ----------------
extern "C" void kernel_launch(void* const* d_in, const int* in_sizes, int n_in,
                              void* d_out, int out_size)
{
    const float* x   = (const float*)d_in[0];
    const float* Wih[3] = { (const float*)d_in[1], (const float*)d_in[4], (const float*)d_in[7] };
    const float* Whh[3] = { (const float*)d_in[2], (const float*)d_in[5], (const float*)d_in[8] };
    const float* bgt[3] = { (const float*)d_in[3], (const float*)d_in[6], (const float*)d_in[9] };
    const float* Wp  = (const float*)d_in[10];

    float *pre, *proj;
    __nv_bfloat16 *p0h, *p0l, *p1h, *p1l, *bh, *bl, *pph, *ppl, *hbp;
    cudaGetSymbolAddress((void**)&pre,  g_pre);
    cudaGetSymbolAddress((void**)&proj, g_proj);
    cudaGetSymbolAddress((void**)&hbp,  g_hb);
    cudaGetSymbolAddress((void**)&p0h,  g_p0h);
    cudaGetSymbolAddress((void**)&p0l,  g_p0l);
    cudaGetSymbolAddress((void**)&p1h,  g_p1h);
    cudaGetSymbolAddress((void**)&p1l,  g_p1l);
    cudaGetSymbolAddress((void**)&bh,   g_bh);
    cudaGetSymbolAddress((void**)&bl,   g_bl);
    cudaGetSymbolAddress((void**)&pph,  g_ph);
    cudaGetSymbolAddress((void**)&ppl,  g_pl);

    cudaFuncSetAttribute(lstm_persist, cudaFuncAttributeMaxDynamicSharedMemorySize, RSMEM);
    cudaFuncSetAttribute(gemm_mma3, cudaFuncAttributeMaxDynamicSharedMemorySize, GSMEM);

    // pair0 holds x split; lstm L writes pair[(L+1)&1]:
    //   L0: gemm(pair0) -> lstm writes pair1 (res none)
    //   L1: gemm(pair1) -> lstm writes pair0 (res pair1)
    //   L2: gemm(pair0) -> lstm writes pair1 (res pair0)
    //   proj: gemm(pair1)
    __nv_bfloat16* prh[2] = { p0h, p1h };
    __nv_bfloat16* prl[2] = { p0l, p1l };

    split_x_tmajor<<<4096, 256>>>(x, p0h, p0l);

    int K = INF;
    for (int L = 0; L < 3; L++) {
        int in = L & 1;          // pair read by GEMM: 0,1,0
        int outp = in ^ 1;       // pair written by lstm: 1,0,1
        split_bf16<<<512, 256>>>(Wih[L], bh, bl, (size_t)GG * K / 4);

        dim3 grid(GG / 128, MM / 128);
        gemm_mma3<<<grid, 256, GSMEM>>>(prh[in], prl[in], bh, bl, bgt[L], pre, K, GG);

        const __nv_bfloat16* rh = (L > 0) ? prh[in] : nullptr;
        const __nv_bfloat16* rl = (L > 0) ? prl[in] : nullptr;
        lstm_persist<<<NCTA, 256, RSMEM>>>(pre, Whh[L], hbp,
                                           prh[outp], prl[outp], rh, rl);
        K = HH;
    }

    // projection reads pair1 (layer-3 output)
    pad_wp_split<<<96, 256>>>(pph, ppl, Wp);
    dim3 gridP(1, MM / 128);
    gemm_mma3<<<gridP, 256, GSMEM>>>(p1h, p1l, pph, ppl, nullptr, proj, HH, 128);
    copy_out<<<1024, 256>>>((float*)d_out, proj, MM * OUTD);
}

// round 17
// speedup vs baseline: 1.0251x; 1.0251x over previous
#include <cuda_runtime.h>
#include <cuda_bf16.h>
#include <math.h>
#include <stdint.h>

#define BB 64
#define TT 1024
#define INF 512
#define HH 768
#define GG 3072          // 4*H
#define MM (BB*TT)       // 65536
#define OUTD 100
#define BBHH (BB*HH)

// recurrence config
#define NCTA 128
#define JC 6             // h columns per CTA
#define NC 24            // gate rows per CTA (4*JC)
#define KCH 128          // k per chunk
#define WROWB 1552       // W smem row pitch bytes (768*2 + 16)
#define HROW2 272        // h tile row pitch bytes (128*2 + 16)
#define HTILE2 (64*HROW2) // 17408
#define WTILE (NC*WROWB) // 37248
#define RSMEM (2*WTILE + 6*HTILE2 + 2*64*28*4)   // 193280

// GEMM config: tile 256(M) x 128(N), 512 threads, ring-2
#define HROWB 144        // GEMM tile row pitch (64*2 + 16)
#define GAT_B (128*HROWB)  // 18432: one 128x64 bf16 tile
#define GAT_A (256*HROWB)  // 36864: one 256x64 bf16 tile
#define GSTAGE (2*GAT_A + 2*GAT_B)  // Ah, Al, Bh, Bl = 110592
#define GSMEM (2*GSTAGE)            // 221184

// ---------------- scratch (device globals; no allocation allowed) ----------------
// t-major layout: row(b,t) = t*BB + b
__device__ float g_pre[(size_t)MM * GG];
__device__ float g_proj[(size_t)MM * 128];
__device__ __nv_bfloat16 g_hb[2][BBHH];      // [parity] hi only
__device__ unsigned g_count = 0;             // grid barrier arrivals
__device__ unsigned g_epoch = 0;             // grid barrier epoch (monotonic)
// activation hi/lo pairs (ping-pong between layers), t-major rows
__device__ __nv_bfloat16 g_p0h[(size_t)MM * HH];
__device__ __nv_bfloat16 g_p0l[(size_t)MM * HH];
__device__ __nv_bfloat16 g_p1h[(size_t)MM * HH];
__device__ __nv_bfloat16 g_p1l[(size_t)MM * HH];
// weight splits
__device__ __nv_bfloat16 g_bh[(size_t)GG * HH];
__device__ __nv_bfloat16 g_bl[(size_t)GG * HH];
__device__ __nv_bfloat16 g_ph[128 * HH];
__device__ __nv_bfloat16 g_pl[128 * HH];

// ---------------- ptx helpers (base sm_103 ISA only) ----------------
__device__ __forceinline__ void cpasync16(uint32_t saddr, const void* g) {
    asm volatile("cp.async.cg.shared.global [%0], [%1], 16;\n" :: "r"(saddr), "l"(g));
}
__device__ __forceinline__ void cpcommit() { asm volatile("cp.async.commit_group;\n"); }
template<int N> __device__ __forceinline__ void cpwait() {
    asm volatile("cp.async.wait_group %0;\n" :: "n"(N));
}
__device__ __forceinline__ uint32_t smem_u32(const void* p) {
    return (uint32_t)__cvta_generic_to_shared(p);
}
__device__ __forceinline__ void barsync(int id) {
    asm volatile("bar.sync %0, 128;" :: "r"(id) : "memory");
}
__device__ __forceinline__ void ldsm4(uint32_t addr, uint32_t* r) {
    asm volatile("ldmatrix.sync.aligned.m8n8.x4.shared.b16 {%0,%1,%2,%3}, [%4];"
                 : "=r"(r[0]), "=r"(r[1]), "=r"(r[2]), "=r"(r[3]) : "r"(addr));
}
__device__ __forceinline__ void ldsm2(uint32_t addr, uint32_t* r) {
    asm volatile("ldmatrix.sync.aligned.m8n8.x2.shared.b16 {%0,%1}, [%2];"
                 : "=r"(r[0]), "=r"(r[1]) : "r"(addr));
}
__device__ __forceinline__ void mma_bf16(float* d, const uint32_t* a, uint32_t b0, uint32_t b1) {
    asm volatile(
        "mma.sync.aligned.m16n8k16.row.col.f32.bf16.bf16.f32 "
        "{%0,%1,%2,%3}, {%4,%5,%6,%7}, {%8,%9}, {%0,%1,%2,%3};"
        : "+f"(d[0]), "+f"(d[1]), "+f"(d[2]), "+f"(d[3])
        : "r"(a[0]), "r"(a[1]), "r"(a[2]), "r"(a[3]), "r"(b0), "r"(b1));
}

// fast sigmoid / tanh (clamped, no-NaN; err ~1e-6)
__device__ __forceinline__ float fsigmoid(float x) {
    return __fdividef(1.f, 1.f + __expf(-x));
}
__device__ __forceinline__ float ftanh(float x) {
    x = fminf(15.f, fmaxf(-15.f, x));
    float e2 = __expf(2.f * x);
    return __fdividef(e2 - 1.f, e2 + 1.f);
}

// ---------------- software grid barrier (proven flat atomic) ----------------
__device__ __forceinline__ void grid_barrier(unsigned e0, unsigned target) {
    __threadfence();
    __syncthreads();
    if (threadIdx.x == 0) {
        unsigned a = atomicAdd(&g_count, 1);
        if (a == NCTA - 1) {
            g_count = 0;
            __threadfence();
            atomicAdd(&g_epoch, 1);
        } else {
            while ((*(volatile unsigned*)&g_epoch) - e0 < target) { }
            __threadfence();
        }
    }
    __syncthreads();
}

// ---------------- split conversions ----------------
// transposing split for input x: src rows b*TT+t (b-major) -> dst rows t*BB+b
__global__ void split_x_tmajor(const float* __restrict__ src,
                               __nv_bfloat16* __restrict__ hi,
                               __nv_bfloat16* __restrict__ lo)
{
    const int F4 = INF / 4;   // 128 float4 per row
    size_t n = (size_t)MM * F4;
    size_t i = (size_t)blockIdx.x * blockDim.x + threadIdx.x;
    size_t stride = (size_t)gridDim.x * blockDim.x;
    for (; i < n; i += stride) {
        size_t r = i / F4;
        int off = (int)(i - r * F4);
        int t = (int)(r / BB), b = (int)(r - (size_t)t * BB);
        float4 v = ((const float4*)src)[((size_t)b * TT + t) * F4 + off];
        __nv_bfloat16 h0 = __float2bfloat16(v.x);
        __nv_bfloat16 h1 = __float2bfloat16(v.y);
        __nv_bfloat16 h2 = __float2bfloat16(v.z);
        __nv_bfloat16 h3 = __float2bfloat16(v.w);
        __nv_bfloat162 hp0; hp0.x = h0; hp0.y = h1;
        __nv_bfloat162 hp1; hp1.x = h2; hp1.y = h3;
        __nv_bfloat162 lp0;
        lp0.x = __float2bfloat16(v.x - __bfloat162float(h0));
        lp0.y = __float2bfloat16(v.y - __bfloat162float(h1));
        __nv_bfloat162 lp1;
        lp1.x = __float2bfloat16(v.z - __bfloat162float(h2));
        lp1.y = __float2bfloat16(v.w - __bfloat162float(h3));
        ((__nv_bfloat162*)hi)[2*i]   = hp0;
        ((__nv_bfloat162*)hi)[2*i+1] = hp1;
        ((__nv_bfloat162*)lo)[2*i]   = lp0;
        ((__nv_bfloat162*)lo)[2*i+1] = lp1;
    }
}

__global__ void split_bf16(const float* __restrict__ src,
                           __nv_bfloat16* __restrict__ hi,
                           __nv_bfloat16* __restrict__ lo, size_t n4)
{
    size_t i = (size_t)blockIdx.x * blockDim.x + threadIdx.x;
    size_t stride = (size_t)gridDim.x * blockDim.x;
    for (; i < n4; i += stride) {
        float4 v = ((const float4*)src)[i];
        __nv_bfloat16 h0 = __float2bfloat16(v.x);
        __nv_bfloat16 h1 = __float2bfloat16(v.y);
        __nv_bfloat16 h2 = __float2bfloat16(v.z);
        __nv_bfloat16 h3 = __float2bfloat16(v.w);
        __nv_bfloat162 hp0; hp0.x = h0; hp0.y = h1;
        __nv_bfloat162 hp1; hp1.x = h2; hp1.y = h3;
        __nv_bfloat162 lp0;
        lp0.x = __float2bfloat16(v.x - __bfloat162float(h0));
        lp0.y = __float2bfloat16(v.y - __bfloat162float(h1));
        __nv_bfloat162 lp1;
        lp1.x = __float2bfloat16(v.z - __bfloat162float(h2));
        lp1.y = __float2bfloat16(v.w - __bfloat162float(h3));
        ((__nv_bfloat162*)hi)[2*i]   = hp0;
        ((__nv_bfloat162*)hi)[2*i+1] = hp1;
        ((__nv_bfloat162*)lo)[2*i]   = lp0;
        ((__nv_bfloat162*)lo)[2*i+1] = lp1;
    }
}

__global__ void pad_wp_split(__nv_bfloat16* __restrict__ ph,
                             __nv_bfloat16* __restrict__ pl,
                             const float* __restrict__ Wp)
{
    int i = blockIdx.x * blockDim.x + threadIdx.x;
    int stride = gridDim.x * blockDim.x;
    for (; i < 128 * HH; i += stride) {
        int o = i / HH, k = i % HH;
        float v = (o < OUTD) ? Wp[o * HH + k] : 0.f;
        __nv_bfloat16 h = __float2bfloat16(v);
        ph[i] = h;
        pl[i] = __float2bfloat16(v - __bfloat162float(h));
    }
}

// ---------------- bf16x3 GEMM: tile 256x128, 512 threads, ring-2 ----------------
__device__ __forceinline__ void gemm_issue4(uint32_t sb, int stage,
                                            const __nv_bfloat16* Ah, const __nv_bfloat16* Al,
                                            const __nv_bfloat16* Bh, const __nv_bfloat16* Bl,
                                            int m0, int n0, int K, int ck, int tid)
{
    uint32_t base = sb + stage * GSTAGE;
    // A tiles: 256 rows, 2048 granules each
    {
        const __nv_bfloat16* srcA[2] = { Ah + (size_t)m0 * K + ck, Al + (size_t)m0 * K + ck };
#pragma unroll
        for (int tile = 0; tile < 2; tile++) {
            uint32_t dst = base + tile * GAT_A;
            const __nv_bfloat16* src = srcA[tile];
#pragma unroll
            for (int it = 0; it < 4; it++) {
                int idx = it * 512 + tid;
                int row = idx >> 3, seg = idx & 7;
                cpasync16(dst + row * HROWB + seg * 16, src + (size_t)row * K + seg * 8);
            }
        }
    }
    // B tiles: 128 rows, 1024 granules each
    {
        const __nv_bfloat16* srcB[2] = { Bh + (size_t)n0 * K + ck, Bl + (size_t)n0 * K + ck };
#pragma unroll
        for (int tile = 0; tile < 2; tile++) {
            uint32_t dst = base + 2 * GAT_A + tile * GAT_B;
            const __nv_bfloat16* src = srcB[tile];
#pragma unroll
            for (int it = 0; it < 2; it++) {
                int idx = it * 512 + tid;
                int row = idx >> 3, seg = idx & 7;
                cpasync16(dst + row * HROWB + seg * 16, src + (size_t)row * K + seg * 8);
            }
        }
    }
    cpcommit();
}

__global__ __launch_bounds__(512)
void gemm_mma3(const __nv_bfloat16* __restrict__ Ah, const __nv_bfloat16* __restrict__ Al,
               const __nv_bfloat16* __restrict__ Bh, const __nv_bfloat16* __restrict__ Bl,
               const float* __restrict__ bias, float* __restrict__ C,
               int K, int Ntot)
{
    extern __shared__ __align__(128) char gsm[];
    uint32_t sb = smem_u32(gsm);

    int tid = threadIdx.x;
    int lane = tid & 31;
    int wid = tid >> 5;        // 0..15
    int wm = wid & 3;          // m group: rows wm*64
    int wn = wid >> 2;         // n group: cols wn*32
    int m0 = blockIdx.y * 256;
    int n0 = blockIdx.x * 128;

    const int cps = K >> 6;

    float acc[4][4][4];        // mt(16-row frag) x f(8-col frag) x 4
#pragma unroll
    for (int mt = 0; mt < 4; mt++)
#pragma unroll
        for (int f = 0; f < 4; f++)
#pragma unroll
            for (int r = 0; r < 4; r++) acc[mt][f][r] = 0.f;

    int aRow = (lane & 15);
    int aHalf = (lane >> 4) * 16;
    int gB = lane >> 3;
    int bHalf = (gB & 1) * 16;

    gemm_issue4(sb, 0, Ah, Al, Bh, Bl, m0, n0, K, 0, tid);
    if (cps > 1) gemm_issue4(sb, 1, Ah, Al, Bh, Bl, m0, n0, K, 64, tid);

    for (int c = 0; c < cps; c++) {
        int stage = c & 1;
        if (c + 1 < cps) cpwait<1>(); else cpwait<0>();
        __syncthreads();
        uint32_t tAh = sb + stage * GSTAGE;
        uint32_t tAl = tAh + GAT_A;
        uint32_t tBh = tAh + 2 * GAT_A;
        uint32_t tBl = tBh + GAT_B;
#pragma unroll
        for (int kk = 0; kk < 4; kk++) {
            uint32_t ah[4][4], al[4][4];
#pragma unroll
            for (int mt = 0; mt < 4; mt++) {
                ldsm4(tAh + (wm*64 + mt*16 + aRow) * HROWB + aHalf + kk*32, ah[mt]);
                ldsm4(tAl + (wm*64 + mt*16 + aRow) * HROWB + aHalf + kk*32, al[mt]);
            }
            uint32_t bh[4][2], bl[4][2];
#pragma unroll
            for (int fp = 0; fp < 2; fp++) {
                int fi = fp * 2 + (gB >> 1);
                uint32_t roff = (wn*32 + fi*8 + (lane & 7)) * HROWB + bHalf + kk*32;
                uint32_t r4[4];
                ldsm4(tBh + roff, r4);
                bh[fp*2][0]   = r4[0]; bh[fp*2][1]   = r4[1];
                bh[fp*2+1][0] = r4[2]; bh[fp*2+1][1] = r4[3];
                ldsm4(tBl + roff, r4);
                bl[fp*2][0]   = r4[0]; bl[fp*2][1]   = r4[1];
                bl[fp*2+1][0] = r4[2]; bl[fp*2+1][1] = r4[3];
            }
#pragma unroll
            for (int mt = 0; mt < 4; mt++)
#pragma unroll
                for (int f = 0; f < 4; f++) {
                    mma_bf16(acc[mt][f], ah[mt], bh[f][0], bh[f][1]);
                    mma_bf16(acc[mt][f], ah[mt], bl[f][0], bl[f][1]);
                    mma_bf16(acc[mt][f], al[mt], bh[f][0], bh[f][1]);
                }
        }
        __syncthreads();
        if (c + 2 < cps)
            gemm_issue4(sb, stage, Ah, Al, Bh, Bl, m0, n0, K, (c + 2) * 64, tid);
    }

    int g4 = lane >> 2, tig = lane & 3;
#pragma unroll
    for (int mt = 0; mt < 4; mt++) {
#pragma unroll
        for (int f = 0; f < 4; f++) {
            int r0 = m0 + wm*64 + mt*16 + g4;
            int c0 = n0 + wn*32 + f*8 + tig*2;
            float b0 = bias ? bias[c0] : 0.f;
            float b1 = bias ? bias[c0+1] : 0.f;
            float2 v0; v0.x = acc[mt][f][0] + b0; v0.y = acc[mt][f][1] + b1;
            float2 v1; v1.x = acc[mt][f][2] + b0; v1.y = acc[mt][f][3] + b1;
            *(float2*)&C[(size_t)r0 * Ntot + c0] = v0;
            *(float2*)&C[(size_t)(r0 + 8) * Ntot + c0] = v1;
        }
    }
}

// ---------------- persistent LSTM (R14/R16-proven, unchanged) ----------------
__device__ __forceinline__ void rec_issue(uint32_t hbA, int slot,
                                          const __nv_bfloat16* hhi,
                                          int k0, int ltid)
{
    uint32_t dH = hbA + slot * HTILE2;
#pragma unroll
    for (int it = 0; it < 8; it++) {
        int idx = it * 128 + ltid;        // 1024 granules, 128 threads
        int row = idx >> 4, seg = idx & 15;
        cpasync16(dH + row * HROW2 + seg * 16, hhi + (size_t)row * HH + k0 + seg * 8);
    }
    cpcommit();
}

__global__ __launch_bounds__(256, 1)
void lstm_persist(const float* __restrict__ pre, const float* __restrict__ Whh,
                  __nv_bfloat16* __restrict__ hb,
                  __nv_bfloat16* __restrict__ yh, __nv_bfloat16* __restrict__ yl,
                  const __nv_bfloat16* __restrict__ resh,
                  const __nv_bfloat16* __restrict__ resl)
{
    extern __shared__ __align__(128) char rsm[];
    char* Whi = rsm;
    char* Wlo = rsm + WTILE;
    char* Hb  = rsm + 2 * WTILE;                        // 6 slots, hi only
    float* Csm0 = (float*)(rsm + 2 * WTILE + 6 * HTILE2);
    float* Csm1 = Csm0 + 64 * 28;

    int tid = threadIdx.x;
    int lane = tid & 31;
    int wid = tid >> 5;
    int gid = wid >> 2;          // warp group 0/1
    int w = wid & 3;             // row group within warp group
    int ltid = tid & 127;
    int j0 = blockIdx.x * JC;
    unsigned e0 = 0;
    if (tid == 0) e0 = *(volatile unsigned*)&g_epoch;

    float* CsmMy = gid ? Csm1 : Csm0;

    // cache Whh slice as bf16 hi/lo. SMEM row r = gate r/JC, col j0 + r%JC.
    for (int i = tid; i < NC * HH; i += 256) {
        int r = i / HH, k = i - r * HH;
        int g = r / JC, jj = r - g * JC;
        float v = Whh[(size_t)(g * HH + j0 + jj) * HH + k];
        __nv_bfloat16 h = __float2bfloat16(v);
        ((__nv_bfloat16*)(Whi + r * WROWB))[k] = h;
        ((__nv_bfloat16*)(Wlo + r * WROWB))[k] = __float2bfloat16(v - __bfloat162float(h));
    }

    // zero h (parity 0) for owned columns
    if (tid < BB) {
        __nv_bfloat16 z = __float2bfloat16(0.f);
#pragma unroll
        for (int jj = 0; jj < JC; jj++)
            hb[tid * HH + j0 + jj] = z;
    }
    grid_barrier(e0, 1);

    uint32_t hbA = smem_u32(Hb);
    uint32_t wA[2] = { smem_u32(Whi), smem_u32(Wlo) };

    // ldmatrix address components (proven layout)
    int aRow = (lane & 15);
    int aHalf = (lane >> 4) * 16;
    int gB = lane >> 3;
    int fi01 = (gB >> 1) * 8 + (lane & 7);
    int bHalf01 = (gB & 1) * 16;
    int row2 = 16 + (lane & 7);
    int bHalf2 = ((lane >> 3) & 1) * 16;
    int g4 = lane >> 2, tig = lane & 3;

    // cell-update partition
    int b0c = tid / JC, j0c = tid - b0c * JC;
    int b1c = (256 + tid) / JC, j1c = (256 + tid) - b1c * JC;
    bool has2 = (tid < 128);
    float cr0 = 0.f, cr1 = 0.f;

    // preload pre/res for t=0
    float pr0[4], pr1[4], rv0 = 0.f, rv1 = 0.f;
    {
        int jj = j0 + j0c;
        size_t prow = (size_t)b0c * GG;   // t=0: row = b
        pr0[0] = pre[prow + 0*HH + jj];
        pr0[1] = pre[prow + 1*HH + jj];
        pr0[2] = pre[prow + 2*HH + jj];
        pr0[3] = pre[prow + 3*HH + jj];
        if (resh) {
            size_t ri = (size_t)b0c * HH + jj;
            rv0 = __bfloat162float(resh[ri]) + __bfloat162float(resl[ri]);
        }
    }
    if (has2) {
        int jj = j0 + j1c;
        size_t prow = (size_t)b1c * GG;
        pr1[0] = pre[prow + 0*HH + jj];
        pr1[1] = pre[prow + 1*HH + jj];
        pr1[2] = pre[prow + 2*HH + jj];
        pr1[3] = pre[prow + 3*HH + jj];
        if (resh) {
            size_t ri = (size_t)b1c * HH + jj;
            rv1 = __bfloat162float(resh[ri]) + __bfloat162float(resl[ri]);
        }
    }

    for (int t = 0; t < TT; t++) {
        int pin = t & 1;
        const __nv_bfloat16* hin = hb + (size_t)pin * BBHH;
        __nv_bfloat16* hout = hb + (size_t)(pin ^ 1) * BBHH;

        // issue all 3 group chunks up-front (slots gid*3 .. gid*3+2)
        rec_issue(hbA, gid * 3 + 0, hin, (gid * 3 + 0) * KCH, ltid);
        rec_issue(hbA, gid * 3 + 1, hin, (gid * 3 + 1) * KCH, ltid);
        rec_issue(hbA, gid * 3 + 2, hin, (gid * 3 + 2) * KCH, ltid);

        float acc[3][4];
#pragma unroll
        for (int f = 0; f < 3; f++)
#pragma unroll
            for (int r = 0; r < 4; r++) acc[f][r] = 0.f;

        // group-local chunk loop: 3 chunks, one barsync each
#pragma unroll
        for (int i = 0; i < 3; i++) {
            int c = gid * 3 + i;
            int slot = gid * 3 + i;
            if (i == 0) cpwait<2>();
            else if (i == 1) cpwait<1>();
            else cpwait<0>();
            barsync(1 + gid);
            uint32_t Abase = hbA + slot * HTILE2;
            uint32_t Whc = wA[0] + c * 256;
            uint32_t Wlc = wA[1] + c * 256;
#pragma unroll
            for (int kk = 0; kk < 8; kk++) {
                uint32_t a[4];
                ldsm4(Abase + (w*16 + aRow) * HROW2 + aHalf + kk*32, a);
                uint32_t bh01[4], bh2[2], bl01[4], bl2[2];
                ldsm4(Whc + fi01 * WROWB + bHalf01 + kk*32, bh01);
                ldsm2(Whc + row2 * WROWB + bHalf2 + kk*32, bh2);
                ldsm4(Wlc + fi01 * WROWB + bHalf01 + kk*32, bl01);
                ldsm2(Wlc + row2 * WROWB + bHalf2 + kk*32, bl2);
                mma_bf16(acc[0], a, bh01[0], bh01[1]);
                mma_bf16(acc[1], a, bh01[2], bh01[3]);
                mma_bf16(acc[2], a, bh2[0], bh2[1]);
                mma_bf16(acc[0], a, bl01[0], bl01[1]);
                mma_bf16(acc[1], a, bl01[2], bl01[3]);
                mma_bf16(acc[2], a, bl2[0], bl2[1]);
            }
        }

        // write partial gate tile to this group's Csm region
#pragma unroll
        for (int f = 0; f < 3; f++) {
            CsmMy[(w*16 + g4) * 28 + f*8 + tig*2]     = acc[f][0];
            CsmMy[(w*16 + g4) * 28 + f*8 + tig*2 + 1] = acc[f][1];
            CsmMy[(w*16 + 8 + g4) * 28 + f*8 + tig*2]     = acc[f][2];
            CsmMy[(w*16 + 8 + g4) * 28 + f*8 + tig*2 + 1] = acc[f][3];
        }
        __syncthreads();

        // cell update (c in registers); y written as bf16 hi/lo only (t-major)
        {
            int b = b0c, jj = j0c, j = j0 + jj;
            float gi = Csm0[b*28 + 0*JC + jj] + Csm1[b*28 + 0*JC + jj] + pr0[0];
            float gf = Csm0[b*28 + 1*JC + jj] + Csm1[b*28 + 1*JC + jj] + pr0[1];
            float gg = Csm0[b*28 + 2*JC + jj] + Csm1[b*28 + 2*JC + jj] + pr0[2];
            float go = Csm0[b*28 + 3*JC + jj] + Csm1[b*28 + 3*JC + jj] + pr0[3];
            float si = fsigmoid(gi), sf_ = fsigmoid(gf), so = fsigmoid(go);
            float tg = ftanh(gg);
            float cn = sf_ * cr0 + si * tg;
            float hn = so * ftanh(cn);
            cr0 = cn;
            hout[b * HH + j] = __float2bfloat16(hn);
            float yv = resh ? hn + rv0 : hn;
            size_t yi = ((size_t)t * BB + b) * HH + j;
            __nv_bfloat16 vh = __float2bfloat16(yv);
            yh[yi] = vh;
            yl[yi] = __float2bfloat16(yv - __bfloat162float(vh));
        }
        if (has2) {
            int b = b1c, jj = j1c, j = j0 + jj;
            float gi = Csm0[b*28 + 0*JC + jj] + Csm1[b*28 + 0*JC + jj] + pr1[0];
            float gf = Csm0[b*28 + 1*JC + jj] + Csm1[b*28 + 1*JC + jj] + pr1[1];
            float gg = Csm0[b*28 + 2*JC + jj] + Csm1[b*28 + 2*JC + jj] + pr1[2];
            float go = Csm0[b*28 + 3*JC + jj] + Csm1[b*28 + 3*JC + jj] + pr1[3];
            float si = fsigmoid(gi), sf_ = fsigmoid(gf), so = fsigmoid(go);
            float tg = ftanh(gg);
            float cn = sf_ * cr1 + si * tg;
            float hn = so * ftanh(cn);
            cr1 = cn;
            hout[b * HH + j] = __float2bfloat16(hn);
            float yv = resh ? hn + rv1 : hn;
            size_t yi = ((size_t)t * BB + b) * HH + j;
            __nv_bfloat16 vh = __float2bfloat16(yv);
            yh[yi] = vh;
            yl[yi] = __float2bfloat16(yv - __bfloat162float(vh));
        }

        // issue next step's pre/res loads BEFORE the barrier (dense t-major rows)
        if (t + 1 < TT) {
            int tn = t + 1;
            {
                int jj = j0 + j0c;
                size_t prow = ((size_t)tn * BB + b0c) * GG;
                pr0[0] = pre[prow + 0*HH + jj];
                pr0[1] = pre[prow + 1*HH + jj];
                pr0[2] = pre[prow + 2*HH + jj];
                pr0[3] = pre[prow + 3*HH + jj];
                if (resh) {
                    size_t ri = ((size_t)tn * BB + b0c) * HH + jj;
                    rv0 = __bfloat162float(resh[ri]) + __bfloat162float(resl[ri]);
                }
            }
            if (has2) {
                int jj = j0 + j1c;
                size_t prow = ((size_t)tn * BB + b1c) * GG;
                pr1[0] = pre[prow + 0*HH + jj];
                pr1[1] = pre[prow + 1*HH + jj];
                pr1[2] = pre[prow + 2*HH + jj];
                pr1[3] = pre[prow + 3*HH + jj];
                if (resh) {
                    size_t ri = ((size_t)tn * BB + b1c) * HH + jj;
                    rv1 = __bfloat162float(resh[ri]) + __bfloat162float(resl[ri]);
                }
            }
        }
        grid_barrier(e0, t + 2);
    }
}

// ---------------- output copy (un-permute t-major -> b-major) ----------------
__global__ void copy_out(float* __restrict__ out, const float* __restrict__ proj, int n)
{
    int i = blockIdx.x * blockDim.x + threadIdx.x;
    int stride = gridDim.x * blockDim.x;
    for (; i < n; i += stride) {
        int m = i / OUTD, o = i - m * OUTD;    // m = b*TT + t (output order)
        int b = m / TT, t = m - b * TT;
        out[i] = proj[((size_t)t * BB + b) * 128 + o];
    }
}

// ---------------- driver ----------------
extern "C" void kernel_launch(void* const* d_in, const int* in_sizes, int n_in,
                              void* d_out, int out_size)
{
    const float* x   = (const float*)d_in[0];
    const float* Wih[3] = { (const float*)d_in[1], (const float*)d_in[4], (const float*)d_in[7] };
    const float* Whh[3] = { (const float*)d_in[2], (const float*)d_in[5], (const float*)d_in[8] };
    const float* bgt[3] = { (const float*)d_in[3], (const float*)d_in[6], (const float*)d_in[9] };
    const float* Wp  = (const float*)d_in[10];

    float *pre, *proj;
    __nv_bfloat16 *p0h, *p0l, *p1h, *p1l, *bh, *bl, *pph, *ppl, *hbp;
    cudaGetSymbolAddress((void**)&pre,  g_pre);
    cudaGetSymbolAddress((void**)&proj, g_proj);
    cudaGetSymbolAddress((void**)&hbp,  g_hb);
    cudaGetSymbolAddress((void**)&p0h,  g_p0h);
    cudaGetSymbolAddress((void**)&p0l,  g_p0l);
    cudaGetSymbolAddress((void**)&p1h,  g_p1h);
    cudaGetSymbolAddress((void**)&p1l,  g_p1l);
    cudaGetSymbolAddress((void**)&bh,   g_bh);
    cudaGetSymbolAddress((void**)&bl,   g_bl);
    cudaGetSymbolAddress((void**)&pph,  g_ph);
    cudaGetSymbolAddress((void**)&ppl,  g_pl);

    cudaFuncSetAttribute(lstm_persist, cudaFuncAttributeMaxDynamicSharedMemorySize, RSMEM);
    cudaFuncSetAttribute(gemm_mma3, cudaFuncAttributeMaxDynamicSharedMemorySize, GSMEM);

    // pair0 holds x split; lstm L writes pair[(L+1)&1]:
    //   L0: gemm(pair0) -> lstm writes pair1 (res none)
    //   L1: gemm(pair1) -> lstm writes pair0 (res pair1)
    //   L2: gemm(pair0) -> lstm writes pair1 (res pair0)
    //   proj: gemm(pair1)
    __nv_bfloat16* prh[2] = { p0h, p1h };
    __nv_bfloat16* prl[2] = { p0l, p1l };

    split_x_tmajor<<<4096, 256>>>(x, p0h, p0l);

    int K = INF;
    for (int L = 0; L < 3; L++) {
        int in = L & 1;          // pair read by GEMM: 0,1,0
        int outp = in ^ 1;       // pair written by lstm: 1,0,1
        split_bf16<<<512, 256>>>(Wih[L], bh, bl, (size_t)GG * K / 4);

        dim3 grid(GG / 128, MM / 256);
        gemm_mma3<<<grid, 512, GSMEM>>>(prh[in], prl[in], bh, bl, bgt[L], pre, K, GG);

        const __nv_bfloat16* rh = (L > 0) ? prh[in] : nullptr;
        const __nv_bfloat16* rl = (L > 0) ? prl[in] : nullptr;
        lstm_persist<<<NCTA, 256, RSMEM>>>(pre, Whh[L], hbp,
                                           prh[outp], prl[outp], rh, rl);
        K = HH;
    }

    // projection reads pair1 (layer-3 output)
    pad_wp_split<<<96, 256>>>(pph, ppl, Wp);
    dim3 gridP(1, MM / 256);
    gemm_mma3<<<gridP, 512, GSMEM>>>(p1h, p1l, pph, ppl, nullptr, proj, HH, 128);
    copy_out<<<1024, 256>>>((float*)d_out, proj, MM * OUTD);
}